// round 10
// baseline (speedup 1.0000x reference)
#include <cuda_runtime.h>
#include <cuda_fp16.h>
#include <math.h>
#include <stdint.h>

#define NB     4096
#define NROWS  8192
#define DDIM   128
#define NTILE  64          // 8192 / 128
#define NCTA   2080        // NTILE*(NTILE+1)/2 upper-triangle tiles
#define E2LOG2 2.885390081777927f   // 2 * log2(e)

// ---------------- static scratch (no allocations allowed) ----------------
__device__ uint8_t g8[NROWS * DDIM];    // e4m3 normalized reps
__device__ float   g_rowsum[NROWS];
__device__ float   g_pos[NROWS];
__device__ float   g_self[NROWS];

// ---------------- helpers ----------------
__device__ __forceinline__ uint32_t smem_u32(const void* p) {
    uint32_t a;
    asm("{ .reg .u64 t; cvta.to.shared.u64 t, %1; cvt.u32.u64 %0, t; }"
        : "=r"(a) : "l"(p));
    return a;
}
__device__ __forceinline__ void ldsm4(uint32_t* r, uint32_t addr) {
    asm volatile("ldmatrix.sync.aligned.m8n8.x4.shared.b16 {%0,%1,%2,%3}, [%4];"
                 : "=r"(r[0]), "=r"(r[1]), "=r"(r[2]), "=r"(r[3]) : "r"(addr));
}
// fp8 e4m3 MMA, f32 accumulate
__device__ __forceinline__ void mma_f8(float* d, const uint32_t* a,
                                       uint32_t b0, uint32_t b1) {
    asm volatile("mma.sync.aligned.m16n8k32.row.col.f32.e4m3.e4m3.f32 "
                 "{%0,%1,%2,%3}, {%4,%5,%6,%7}, {%8,%9}, {%0,%1,%2,%3};"
                 : "+f"(d[0]), "+f"(d[1]), "+f"(d[2]), "+f"(d[3])
                 : "r"(a[0]), "r"(a[1]), "r"(a[2]), "r"(a[3]), "r"(b0), "r"(b1));
}
__device__ __forceinline__ uint32_t hadd2(uint32_t a, uint32_t b) {
    uint32_t o; asm("add.rn.f16x2 %0, %1, %2;" : "=r"(o) : "r"(a), "r"(b)); return o;
}
__device__ __forceinline__ uint32_t hex2(uint32_t a) {
    uint32_t o; asm("ex2.approx.f16x2 %0, %1;" : "=r"(o) : "r"(a)); return o;
}
// pack two f32 -> f16x2 (lo = first arg)
__device__ __forceinline__ uint32_t pack_h2(float lo, float hi) {
    uint32_t o;
    asm("cvt.rn.f16x2.f32 %0, %1, %2;" : "=r"(o) : "f"(hi), "f"(lo));
    return o;
}
__device__ __forceinline__ float2 h2f2(uint32_t h) {
    __half2 v = *reinterpret_cast<__half2*>(&h);
    return __half22float2(v);
}
// pack 4 f32 -> 4 e4m3 bytes (byte0 = x)
__device__ __forceinline__ uint32_t pack_e4m3x4(float x, float y, float z, float w) {
    uint16_t lo, hi;
    asm("cvt.rn.satfinite.e4m3x2.f32 %0, %1, %2;" : "=h"(lo) : "f"(y), "f"(x));
    asm("cvt.rn.satfinite.e4m3x2.f32 %0, %1, %2;" : "=h"(hi) : "f"(w), "f"(z));
    return (uint32_t)lo | ((uint32_t)hi << 16);
}
__device__ __forceinline__ void cp16(uint32_t dst, const void* src) {
    asm volatile("cp.async.cg.shared.global [%0], [%1], 16;"
                 :: "r"(dst), "l"(src) : "memory");
}
#define CP_COMMIT() asm volatile("cp.async.commit_group;" ::: "memory")
#define CP_WAIT0()  asm volatile("cp.async.wait_group 0;" ::: "memory")

// smem: 128-row A + 128-row B fp8 tiles, pitch 144 B (9x16B -> conflict-free ldmatrix)
#define PITCH    144
#define SM_A     0
#define SM_B     (128 * PITCH)
#define SM_ROWS  (256 * PITCH)
#define SM_COLS  (SM_ROWS + 128 * 4)
#define SMEM_SZ  (SM_COLS + 128 * 4)

// ---------------- K1: normalize pair + e4m3 + positives/self ----------------
__global__ void __launch_bounds__(256) k_norm(const float* __restrict__ p1,
                                              const float* __restrict__ p2,
                                              float* __restrict__ out) {
    int gw = (blockIdx.x * blockDim.x + threadIdx.x) >> 5;   // pair index 0..NB-1
    int lane = threadIdx.x & 31;
    if (gw >= NB) return;
    if (gw == 0 && lane == 0) out[0] = 0.0f;
    float4 v1 = *(const float4*)(p1 + (size_t)gw * DDIM + lane * 4);
    float4 v2 = *(const float4*)(p2 + (size_t)gw * DDIM + lane * 4);
    float ss1 = v1.x*v1.x + v1.y*v1.y + v1.z*v1.z + v1.w*v1.w;
    float ss2 = v2.x*v2.x + v2.y*v2.y + v2.z*v2.z + v2.w*v2.w;
    float cx  = v1.x*v2.x + v1.y*v2.y + v1.z*v2.z + v1.w*v2.w;
#pragma unroll
    for (int o = 16; o; o >>= 1) {
        ss1 += __shfl_xor_sync(0xffffffffu, ss1, o);
        ss2 += __shfl_xor_sync(0xffffffffu, ss2, o);
        cx  += __shfl_xor_sync(0xffffffffu, cx,  o);
    }
    float inv1 = 1.0f / fmaxf(sqrtf(ss1), 1e-12f);
    float inv2 = 1.0f / fmaxf(sqrtf(ss2), 1e-12f);

    *(uint32_t*)(g8 + (size_t)gw * DDIM + lane * 4) =
        pack_e4m3x4(v1.x * inv1, v1.y * inv1, v1.z * inv1, v1.w * inv1);
    *(uint32_t*)(g8 + (size_t)(gw + NB) * DDIM + lane * 4) =
        pack_e4m3x4(v2.x * inv2, v2.y * inv2, v2.z * inv2, v2.w * inv2);

    if (lane == 0) {
        float pos = cx * inv1 * inv2;
        g_pos[gw] = pos;            g_pos[gw + NB] = pos;
        g_self[gw] = ss1 * inv1 * inv1;
        g_self[gw + NB] = ss2 * inv2 * inv2;
        g_rowsum[gw] = 0.0f;        g_rowsum[gw + NB] = 0.0f;
    }
}

// ---------------- K2: FP8 MMA sim-GEMM (upper triangle) ----------------
extern __shared__ char smem_raw[];

__global__ void __launch_bounds__(256, 2) k_gemm() {
    const int tid  = threadIdx.x;
    const int wid  = tid >> 5;
    const int lane = tid & 31;

    // decode upper-triangle tile (bi <= bj) from linear blockIdx
    int t = blockIdx.x;
    int bi = (int)(64.5f - sqrtf(64.5f * 64.5f - 2.0f * (float)t));
    while (bi * NTILE - (bi * (bi - 1)) / 2 > t) --bi;
    while ((bi + 1) * NTILE - ((bi + 1) * bi) / 2 <= t) ++bi;
    const int bj = bi + (t - (bi * NTILE - (bi * (bi - 1)) / 2));
    const bool diag = (bi == bj);
    const int r0 = bi * 128;
    const int c0 = bj * 128;

    const uint32_t sb = smem_u32(smem_raw);
    float* smrows = (float*)(smem_raw + SM_ROWS);
    float* smcols = (float*)(smem_raw + SM_COLS);
    if (tid < 128) { smrows[tid] = 0.0f; smcols[tid] = 0.0f; }

    // async load A (rows r0..+127) + B (rows c0..+127): 256 rows x 8 segs of 16B
#pragma unroll
    for (int it = 0; it < 8; ++it) {
        int idx = tid + it * 256;
        int row = idx >> 3;
        int seg = idx & 7;
        int grow = (row < 128) ? r0 + row : c0 + (row - 128);
        cp16(sb + (uint32_t)(row * PITCH + seg * 16),
             g8 + (size_t)grow * DDIM + seg * 16);
    }
    CP_COMMIT();
    CP_WAIT0();
    __syncthreads();

    const int wm = wid >> 2;          // 0..1 -> rows 64*wm
    const int wn = wid & 3;           // 0..3 -> cols 32*wn

    // A: matrices {rows0-7,16B0}{rows8-15,16B0}{rows0-7,16B1}{rows8-15,16B1} per kk(32B)
    const uint32_t a_base = sb +
        (uint32_t)((64 * wm + (lane & 15)) * PITCH + (lane >> 4) * 16);
    // B: {cols0-7,k0-15}{cols0-7,k16-31}{cols8-15,k0-15}{cols8-15,k16-31}
    const int brow = 32 * wn + (lane & 7) + ((lane >> 4) << 3);
    const uint32_t b_base = sb + SM_B +
        (uint32_t)(brow * PITCH + ((lane >> 3) & 1) * 16);

    float acc[4][4][4];
#pragma unroll
    for (int mi = 0; mi < 4; ++mi)
#pragma unroll
        for (int nj = 0; nj < 4; ++nj)
#pragma unroll
            for (int e = 0; e < 4; ++e) acc[mi][nj][e] = 0.0f;

#pragma unroll
    for (int kk = 0; kk < 4; ++kk) {           // 4 k-blocks of 32
        uint32_t b0[4], b1[4];
        ldsm4(b0, b_base + kk * 32);           // cols 0-15 of this warp's 32
        ldsm4(b1, b_base + 16 * PITCH + kk * 32);  // cols 16-31
#pragma unroll
        for (int mi = 0; mi < 4; ++mi) {
            uint32_t a[4];
            ldsm4(a, a_base + kk * 32 + mi * 16 * PITCH);
            mma_f8(acc[mi][0], a, b0[0], b0[1]);
            mma_f8(acc[mi][1], a, b0[2], b0[3]);
            mma_f8(acc[mi][2], a, b1[0], b1[1]);
            mma_f8(acc[mi][3], a, b1[2], b1[3]);
        }
    }

    // exp(2*sim): scale f32, pack to f16x2, ex2.approx.f16x2 (2 exps per MUFU)
    uint32_t ex[4][4][2];
#pragma unroll
    for (int mi = 0; mi < 4; ++mi)
#pragma unroll
        for (int nj = 0; nj < 4; ++nj) {
            ex[mi][nj][0] = hex2(pack_h2(acc[mi][nj][0] * E2LOG2,
                                         acc[mi][nj][1] * E2LOG2));
            ex[mi][nj][1] = hex2(pack_h2(acc[mi][nj][2] * E2LOG2,
                                         acc[mi][nj][3] * E2LOG2));
        }

    // row partial sums: f16x2 tree over nj, quad shfl-reduce, 1 atomic/row/quad
    const int rbase = 64 * wm + (lane >> 2);
#pragma unroll
    for (int mi = 0; mi < 4; ++mi) {
        uint32_t hlo = hadd2(hadd2(ex[mi][0][0], ex[mi][1][0]),
                             hadd2(ex[mi][2][0], ex[mi][3][0]));
        uint32_t hhi = hadd2(hadd2(ex[mi][0][1], ex[mi][1][1]),
                             hadd2(ex[mi][2][1], ex[mi][3][1]));
        float2 flo = h2f2(hlo), fhi = h2f2(hhi);
        float slo = flo.x + flo.y;
        float shi = fhi.x + fhi.y;
        slo += __shfl_xor_sync(0xffffffffu, slo, 1);
        slo += __shfl_xor_sync(0xffffffffu, slo, 2);
        shi += __shfl_xor_sync(0xffffffffu, shi, 1);
        shi += __shfl_xor_sync(0xffffffffu, shi, 2);
        if ((lane & 3) == 0) {
            atomicAdd(&smrows[rbase + 16 * mi],     slo);
            atomicAdd(&smrows[rbase + 16 * mi + 8], shi);
        }
    }

    // column partial sums (off-diagonal tiles credit the transpose rows)
    if (!diag) {
#pragma unroll
        for (int nj = 0; nj < 4; ++nj) {
            uint32_t v2 = hadd2(hadd2(ex[0][nj][0], ex[0][nj][1]),
                                hadd2(ex[1][nj][0], ex[1][nj][1]));
            v2 = hadd2(v2, hadd2(hadd2(ex[2][nj][0], ex[2][nj][1]),
                                 hadd2(ex[3][nj][0], ex[3][nj][1])));
            float2 f = h2f2(v2);
            float ve = f.x, vo = f.y;   // even / odd columns
            ve += __shfl_down_sync(0xffffffffu, ve, 16);
            ve += __shfl_down_sync(0xffffffffu, ve, 8);
            ve += __shfl_down_sync(0xffffffffu, ve, 4);
            vo += __shfl_down_sync(0xffffffffu, vo, 16);
            vo += __shfl_down_sync(0xffffffffu, vo, 8);
            vo += __shfl_down_sync(0xffffffffu, vo, 4);
            if (lane < 4) {
                atomicAdd(&smcols[32 * wn + 8 * nj + lane * 2],     ve);
                atomicAdd(&smcols[32 * wn + 8 * nj + lane * 2 + 1], vo);
            }
        }
    }
    __syncthreads();
    if (tid < 128) {
        atomicAdd(&g_rowsum[r0 + tid], smrows[tid]);
        if (!diag) atomicAdd(&g_rowsum[c0 + tid], smcols[tid]);
    }
}

// ---------------- K3: final reduction (8 blocks + atomic) ----------------
__global__ void __launch_bounds__(1024) k_final(float* __restrict__ out) {
    __shared__ float red[1024];
    int tid = threadIdx.x;
    int r = blockIdx.x * 1024 + tid;
    float den = g_rowsum[r] - exp2f(E2LOG2 * g_self[r]);
    red[tid] = __logf(den) - 2.0f * g_pos[r];
    __syncthreads();
#pragma unroll
    for (int o = 512; o; o >>= 1) {
        if (tid < o) red[tid] += red[tid + o];
        __syncthreads();
    }
    if (tid == 0) atomicAdd(out, red[0] * (1.0f / (float)NROWS));
}

// ---------------- launcher ----------------
extern "C" void kernel_launch(void* const* d_in, const int* in_sizes, int n_in,
                              void* d_out, int out_size) {
    const float* p1 = (const float*)d_in[0];
    const float* p2 = (const float*)d_in[1];
    float* out = (float*)d_out;

    cudaFuncSetAttribute(k_gemm, cudaFuncAttributeMaxDynamicSharedMemorySize, SMEM_SZ);

    k_norm<<<NB / 8, 256>>>(p1, p2, out);
    k_gemm<<<NCTA, 256, SMEM_SZ>>>();
    k_final<<<NROWS / 1024, 1024>>>(out);
}

// round 11
// speedup vs baseline: 1.2260x; 1.2260x over previous
#include <cuda_runtime.h>
#include <cuda_fp16.h>
#include <math.h>
#include <stdint.h>

#define NB     4096
#define NROWS  8192
#define DDIM   128
#define NTILE  64          // 8192 / 128
#define NCTA   2080        // NTILE*(NTILE+1)/2 upper-triangle tiles
#define E2LOG2 2.885390081777927f   // 2 * log2(e)

// ---------------- static scratch (no allocations allowed) ----------------
__device__ uint8_t g8[NROWS * DDIM];    // e4m3 normalized reps
__device__ float   g_rowsum[NROWS];
__device__ float   g_pos[NROWS];
__device__ float   g_self[NROWS];

// ---------------- helpers ----------------
__device__ __forceinline__ uint32_t smem_u32(const void* p) {
    uint32_t a;
    asm("{ .reg .u64 t; cvta.to.shared.u64 t, %1; cvt.u32.u64 %0, t; }"
        : "=r"(a) : "l"(p));
    return a;
}
__device__ __forceinline__ void ldsm4(uint32_t* r, uint32_t addr) {
    asm volatile("ldmatrix.sync.aligned.m8n8.x4.shared.b16 {%0,%1,%2,%3}, [%4];"
                 : "=r"(r[0]), "=r"(r[1]), "=r"(r[2]), "=r"(r[3]) : "r"(addr));
}
// fp8 e4m3 MMA, f16 accumulate (acc = 2x f16x2)
__device__ __forceinline__ void mma_f8h(uint32_t* d, const uint32_t* a,
                                        uint32_t b0, uint32_t b1) {
    asm volatile("mma.sync.aligned.m16n8k32.row.col.f16.e4m3.e4m3.f16 "
                 "{%0,%1}, {%2,%3,%4,%5}, {%6,%7}, {%0,%1};"
                 : "+r"(d[0]), "+r"(d[1])
                 : "r"(a[0]), "r"(a[1]), "r"(a[2]), "r"(a[3]), "r"(b0), "r"(b1));
}
__device__ __forceinline__ uint32_t hmul2(uint32_t a, uint32_t b) {
    uint32_t o; asm("mul.rn.f16x2 %0, %1, %2;" : "=r"(o) : "r"(a), "r"(b)); return o;
}
__device__ __forceinline__ uint32_t hadd2(uint32_t a, uint32_t b) {
    uint32_t o; asm("add.rn.f16x2 %0, %1, %2;" : "=r"(o) : "r"(a), "r"(b)); return o;
}
__device__ __forceinline__ uint32_t hex2(uint32_t a) {
    uint32_t o; asm("ex2.approx.f16x2 %0, %1;" : "=r"(o) : "r"(a)); return o;
}
__device__ __forceinline__ float2 h2f2(uint32_t h) {
    __half2 v = *reinterpret_cast<__half2*>(&h);
    return __half22float2(v);
}
// pack 4 f32 -> 4 e4m3 bytes (byte0 = x)
__device__ __forceinline__ uint32_t pack_e4m3x4(float x, float y, float z, float w) {
    uint16_t lo, hi;
    asm("cvt.rn.satfinite.e4m3x2.f32 %0, %1, %2;" : "=h"(lo) : "f"(y), "f"(x));
    asm("cvt.rn.satfinite.e4m3x2.f32 %0, %1, %2;" : "=h"(hi) : "f"(w), "f"(z));
    return (uint32_t)lo | ((uint32_t)hi << 16);
}
__device__ __forceinline__ void cp16(uint32_t dst, const void* src) {
    asm volatile("cp.async.cg.shared.global [%0], [%1], 16;"
                 :: "r"(dst), "l"(src) : "memory");
}
#define CP_COMMIT() asm volatile("cp.async.commit_group;" ::: "memory")
#define CP_WAIT0()  asm volatile("cp.async.wait_group 0;" ::: "memory")

// smem: 128-row A + 128-row B fp8 tiles, pitch 144 B (9x16B -> conflict-free ldmatrix)
#define PITCH    144
#define SM_A     0
#define SM_B     (128 * PITCH)
#define SM_ROWS  (256 * PITCH)
#define SM_COLS  (SM_ROWS + 128 * 4)
#define SMEM_SZ  (SM_COLS + 128 * 4)

// ---------------- K1: normalize pair + e4m3 + positives/self ----------------
__global__ void __launch_bounds__(256) k_norm(const float* __restrict__ p1,
                                              const float* __restrict__ p2,
                                              float* __restrict__ out) {
    int gw = (blockIdx.x * blockDim.x + threadIdx.x) >> 5;   // pair index 0..NB-1
    int lane = threadIdx.x & 31;
    if (gw >= NB) return;
    if (gw == 0 && lane == 0) out[0] = 0.0f;
    float4 v1 = *(const float4*)(p1 + (size_t)gw * DDIM + lane * 4);
    float4 v2 = *(const float4*)(p2 + (size_t)gw * DDIM + lane * 4);
    float ss1 = v1.x*v1.x + v1.y*v1.y + v1.z*v1.z + v1.w*v1.w;
    float ss2 = v2.x*v2.x + v2.y*v2.y + v2.z*v2.z + v2.w*v2.w;
    float cx  = v1.x*v2.x + v1.y*v2.y + v1.z*v2.z + v1.w*v2.w;
#pragma unroll
    for (int o = 16; o; o >>= 1) {
        ss1 += __shfl_xor_sync(0xffffffffu, ss1, o);
        ss2 += __shfl_xor_sync(0xffffffffu, ss2, o);
        cx  += __shfl_xor_sync(0xffffffffu, cx,  o);
    }
    float inv1 = 1.0f / fmaxf(sqrtf(ss1), 1e-12f);
    float inv2 = 1.0f / fmaxf(sqrtf(ss2), 1e-12f);

    *(uint32_t*)(g8 + (size_t)gw * DDIM + lane * 4) =
        pack_e4m3x4(v1.x * inv1, v1.y * inv1, v1.z * inv1, v1.w * inv1);
    *(uint32_t*)(g8 + (size_t)(gw + NB) * DDIM + lane * 4) =
        pack_e4m3x4(v2.x * inv2, v2.y * inv2, v2.z * inv2, v2.w * inv2);

    if (lane == 0) {
        float pos = cx * inv1 * inv2;
        g_pos[gw] = pos;            g_pos[gw + NB] = pos;
        g_self[gw] = ss1 * inv1 * inv1;
        g_self[gw + NB] = ss2 * inv2 * inv2;
        g_rowsum[gw] = 0.0f;        g_rowsum[gw + NB] = 0.0f;
    }
}

// ---------------- K2: FP8 MMA (f16 acc) sim-GEMM, 3 CTAs/SM ----------------
extern __shared__ char smem_raw[];

__global__ void __launch_bounds__(256, 3) k_gemm() {
    const int tid  = threadIdx.x;
    const int wid  = tid >> 5;
    const int lane = tid & 31;

    // decode upper-triangle tile (bi <= bj) from linear blockIdx
    int t = blockIdx.x;
    int bi = (int)(64.5f - sqrtf(64.5f * 64.5f - 2.0f * (float)t));
    while (bi * NTILE - (bi * (bi - 1)) / 2 > t) --bi;
    while ((bi + 1) * NTILE - ((bi + 1) * bi) / 2 <= t) ++bi;
    const int bj = bi + (t - (bi * NTILE - (bi * (bi - 1)) / 2));
    const bool diag = (bi == bj);
    const int r0 = bi * 128;
    const int c0 = bj * 128;

    const uint32_t sb = smem_u32(smem_raw);
    float* smrows = (float*)(smem_raw + SM_ROWS);
    float* smcols = (float*)(smem_raw + SM_COLS);
    if (tid < 128) { smrows[tid] = 0.0f; smcols[tid] = 0.0f; }

    // async load A (rows r0..+127) + B (rows c0..+127): 256 rows x 8 segs of 16B
#pragma unroll
    for (int it = 0; it < 8; ++it) {
        int idx = tid + it * 256;
        int row = idx >> 3;
        int seg = idx & 7;
        int grow = (row < 128) ? r0 + row : c0 + (row - 128);
        cp16(sb + (uint32_t)(row * PITCH + seg * 16),
             g8 + (size_t)grow * DDIM + seg * 16);
    }
    CP_COMMIT();
    CP_WAIT0();
    __syncthreads();

    const int wm = wid >> 2;          // 0..1 -> rows 64*wm
    const int wn = wid & 3;           // 0..3 -> cols 32*wn

    const uint32_t a_base = sb +
        (uint32_t)((64 * wm + (lane & 15)) * PITCH + (lane >> 4) * 16);
    const int brow = 32 * wn + (lane & 7) + ((lane >> 4) << 3);
    const uint32_t b_base = sb + SM_B +
        (uint32_t)(brow * PITCH + ((lane >> 3) & 1) * 16);

    uint32_t acc[4][4][2];            // f16x2 accumulators
#pragma unroll
    for (int mi = 0; mi < 4; ++mi)
#pragma unroll
        for (int nj = 0; nj < 4; ++nj) { acc[mi][nj][0] = 0u; acc[mi][nj][1] = 0u; }

#pragma unroll
    for (int kk = 0; kk < 4; ++kk) {           // 4 k-blocks of 32
        uint32_t b0[4], b1[4];
        ldsm4(b0, b_base + kk * 32);           // cols 0-15 of this warp's 32
        ldsm4(b1, b_base + 16 * PITCH + kk * 32);  // cols 16-31
#pragma unroll
        for (int mi = 0; mi < 4; ++mi) {
            uint32_t a[4];
            ldsm4(a, a_base + kk * 32 + mi * 16 * PITCH);
            mma_f8h(acc[mi][0], a, b0[0], b0[1]);
            mma_f8h(acc[mi][1], a, b0[2], b0[3]);
            mma_f8h(acc[mi][2], a, b1[0], b1[1]);
            mma_f8h(acc[mi][3], a, b1[2], b1[3]);
        }
    }

    // exp(2*sim) = exp2(E2LOG2 * sim) in f16x2 (2 exps per MUFU op)
    const __half2 sc2h = __float2half2_rn(E2LOG2);
    const uint32_t sc2 = *reinterpret_cast<const uint32_t*>(&sc2h);
#pragma unroll
    for (int mi = 0; mi < 4; ++mi)
#pragma unroll
        for (int nj = 0; nj < 4; ++nj) {
            acc[mi][nj][0] = hex2(hmul2(acc[mi][nj][0], sc2));
            acc[mi][nj][1] = hex2(hmul2(acc[mi][nj][1], sc2));
        }

    // row partial sums: f16x2 tree over nj, quad shfl-reduce, 1 atomic/row/quad
    const int rbase = 64 * wm + (lane >> 2);
#pragma unroll
    for (int mi = 0; mi < 4; ++mi) {
        uint32_t hlo = hadd2(hadd2(acc[mi][0][0], acc[mi][1][0]),
                             hadd2(acc[mi][2][0], acc[mi][3][0]));
        uint32_t hhi = hadd2(hadd2(acc[mi][0][1], acc[mi][1][1]),
                             hadd2(acc[mi][2][1], acc[mi][3][1]));
        float2 flo = h2f2(hlo), fhi = h2f2(hhi);
        float slo = flo.x + flo.y;
        float shi = fhi.x + fhi.y;
        slo += __shfl_xor_sync(0xffffffffu, slo, 1);
        slo += __shfl_xor_sync(0xffffffffu, slo, 2);
        shi += __shfl_xor_sync(0xffffffffu, shi, 1);
        shi += __shfl_xor_sync(0xffffffffu, shi, 2);
        if ((lane & 3) == 0) {
            atomicAdd(&smrows[rbase + 16 * mi],     slo);
            atomicAdd(&smrows[rbase + 16 * mi + 8], shi);
        }
    }

    // column partial sums (off-diagonal tiles credit the transpose rows)
    if (!diag) {
#pragma unroll
        for (int nj = 0; nj < 4; ++nj) {
            uint32_t v2 = hadd2(hadd2(acc[0][nj][0], acc[0][nj][1]),
                                hadd2(acc[1][nj][0], acc[1][nj][1]));
            v2 = hadd2(v2, hadd2(hadd2(acc[2][nj][0], acc[2][nj][1]),
                                 hadd2(acc[3][nj][0], acc[3][nj][1])));
            float2 f = h2f2(v2);
            float ve = f.x, vo = f.y;   // even / odd columns
            ve += __shfl_down_sync(0xffffffffu, ve, 16);
            ve += __shfl_down_sync(0xffffffffu, ve, 8);
            ve += __shfl_down_sync(0xffffffffu, ve, 4);
            vo += __shfl_down_sync(0xffffffffu, vo, 16);
            vo += __shfl_down_sync(0xffffffffu, vo, 8);
            vo += __shfl_down_sync(0xffffffffu, vo, 4);
            if (lane < 4) {
                atomicAdd(&smcols[32 * wn + 8 * nj + lane * 2],     ve);
                atomicAdd(&smcols[32 * wn + 8 * nj + lane * 2 + 1], vo);
            }
        }
    }
    __syncthreads();
    if (tid < 128) {
        atomicAdd(&g_rowsum[r0 + tid], smrows[tid]);
        if (!diag) atomicAdd(&g_rowsum[c0 + tid], smcols[tid]);
    }
}

// ---------------- K3: final reduction (8 blocks + atomic) ----------------
__global__ void __launch_bounds__(1024) k_final(float* __restrict__ out) {
    __shared__ float red[1024];
    int tid = threadIdx.x;
    int r = blockIdx.x * 1024 + tid;
    float den = g_rowsum[r] - exp2f(E2LOG2 * g_self[r]);
    red[tid] = __logf(den) - 2.0f * g_pos[r];
    __syncthreads();
#pragma unroll
    for (int o = 512; o; o >>= 1) {
        if (tid < o) red[tid] += red[tid + o];
        __syncthreads();
    }
    if (tid == 0) atomicAdd(out, red[0] * (1.0f / (float)NROWS));
}

// ---------------- launcher ----------------
extern "C" void kernel_launch(void* const* d_in, const int* in_sizes, int n_in,
                              void* d_out, int out_size) {
    const float* p1 = (const float*)d_in[0];
    const float* p2 = (const float*)d_in[1];
    float* out = (float*)d_out;

    cudaFuncSetAttribute(k_gemm, cudaFuncAttributeMaxDynamicSharedMemorySize, SMEM_SZ);

    k_norm<<<NB / 8, 256>>>(p1, p2, out);
    k_gemm<<<NCTA, 256, SMEM_SZ>>>();
    k_final<<<NROWS / 1024, 1024>>>(out);
}